// round 8
// baseline (speedup 1.0000x reference)
#include <cuda_runtime.h>
#include <math.h>

#define Nn 8192
#define Dd 512
#define CAP 256

// ---------------- static device scratch (symbol-access only) ----------------
static __device__ float d_K [(size_t)Nn * Nn];      // log_K on reference fp32 grid
static __device__ float d_alpha[Nn];
static __device__ float d_beta [Nn];
static __device__ float d_alpha_prev[Nn];
static __device__ float d_beta_prev [Nn];
static __device__ float d_xsq[Nn];
static __device__ float d_ysq[Nn];
static __device__ float d_m  [Nn];                  // per-row / per-col max (reused)
static __device__ int   d_cnt[Nn];                  // candidate counters
static __device__ int   d_cidx[(size_t)Nn * CAP];   // candidate indices
static __device__ float d_cz [(size_t)Nn * CAP];    // candidate z values
static __device__ float d_colpart[16 * Nn];         // column max partials
static __device__ int   d_idx[Nn];
static __device__ int   g_done;

// ---- XLA-CPU cephes exp, FMA-CONTRACTED (fast-math contract on aarch64) ----
// vsl.MulAdd / Sub(x, Mul(c,fx)) pairs fuse into fma on the NEON backend.
static __device__ __forceinline__ float exp_fma(float x) {
    x = fminf(x, 88.3762626647950f);
    x = fmaxf(x, -88.3762626647949f);
    float fx = floorf(__fmaf_rn(x, 1.44269504088896341f, 0.5f));
    float r  = __fmaf_rn(fx, -0.693359375f, x);      // x - fx*C1 (fused)
    r        = __fmaf_rn(fx,  2.12194440e-4f, r);    // r - fx*C2, C2=-2.12e-4 (fused)
    float z  = __fmul_rn(r, r);
    float y  = __fmaf_rn(1.9875691500e-4f, r, 1.3981999507e-3f);
    y = __fmaf_rn(y, r, 8.3334519073e-3f);
    y = __fmaf_rn(y, r, 4.1665795894e-2f);
    y = __fmaf_rn(y, r, 1.6666665459e-1f);
    y = __fmaf_rn(y, r, 5.0000001201e-1f);
    y = __fmaf_rn(y, z, r);
    y = __fadd_rn(1.0f, y);
    int n = (int)fx;
    float s = __int_as_float((unsigned)(n + 127) << 23);
    return __fmul_rn(y, s);
}

// ---- XLA-CPU cephes log, FMA-CONTRACTED (S >= 1 here) ----
static __device__ __forceinline__ float log_fma(float x) {
    int bits = __float_as_int(x);
    int e = (bits >> 23) - 126;
    float mant = __int_as_float((bits & 0x007fffff) | 0x3f000000);  // [0.5,1)
    if (mant < 0.707106781186547524f) {
        e -= 1;
        mant = __fadd_rn(__fadd_rn(mant, mant), -1.0f);
    } else {
        mant = __fadd_rn(mant, -1.0f);
    }
    float z = __fmul_rn(mant, mant);
    float y = 7.0376836292e-2f;
    y = __fmaf_rn(y, mant, -1.1514610310e-1f);
    y = __fmaf_rn(y, mant,  1.1676998740e-1f);
    y = __fmaf_rn(y, mant, -1.2420140846e-1f);
    y = __fmaf_rn(y, mant,  1.4249322787e-1f);
    y = __fmaf_rn(y, mant, -1.6668057665e-1f);
    y = __fmaf_rn(y, mant,  2.0000714765e-1f);
    y = __fmaf_rn(y, mant, -2.4999993993e-1f);
    y = __fmaf_rn(y, mant,  3.3333331174e-1f);
    y = __fmul_rn(__fmul_rn(y, mant), z);
    float fe = (float)e;
    y = __fmaf_rn(fe, -2.12194440e-4f, y);
    y = __fmaf_rn(-0.5f, z, y);
    float res = __fadd_rn(mant, y);
    res = __fmaf_rn(fe, 0.693359375f, res);
    return res;
}

// XLA vectorized-reduce epilogue: W=8, shuffle-halving combine.
static __device__ __forceinline__ float combine8(const float* s) {
    float w0 = __fadd_rn(s[0], s[4]);
    float w1 = __fadd_rn(s[1], s[5]);
    float w2 = __fadd_rn(s[2], s[6]);
    float w3 = __fadd_rn(s[3], s[7]);
    float u0 = __fadd_rn(w0, w2);
    float u1 = __fadd_rn(w1, w3);
    return __fadd_rn(u0, u1);
}

// ---------------- init ----------------
__global__ void init_kernel() {
    int i = blockIdx.x * blockDim.x + threadIdx.x;
    if (i < Nn) {
        d_beta[i] = 0.0f; d_alpha[i] = 0.0f;
        d_alpha_prev[i] = __int_as_float(0x7fc00000);
        d_beta_prev [i] = __int_as_float(0x7fc00000);
    }
    if (i == 0) g_done = 0;
}

// ---------------- row squared norms: 8-slot FMA chains (contracted) ---------
__global__ void rowsq_kernel(const float* __restrict__ X0,
                             const float* __restrict__ X1) {
    int half = (gridDim.x * blockDim.x) >> 1;
    int g = blockIdx.x * blockDim.x + threadIdx.x;
    bool second = g >= half;
    int row = second ? (g - half) : g;
    const float* x = (second ? X1 : X0) + (size_t)row * Dd;
    float s[8];
#pragma unroll
    for (int i = 0; i < 8; i++) s[i] = 0.0f;
    for (int k = 0; k < Dd; k += 8) {
#pragma unroll
        for (int i = 0; i < 8; i++) {
            float v = x[k + i];
            s[i] = __fmaf_rn(v, v, s[i]);   // acc+mul contracted to fma
        }
    }
    float r = combine8(s);
    if (second) d_ysq[row] = r; else d_xsq[row] = r;
}

// ---------------- GEMM -> K. dot = sequential-k fp32 FMA chain --------------
// K = fl( -(fl(fl(xsq+ysq) - 2*dot)) / 0.1f )  (honor_division => true fdiv)
__global__ void __launch_bounds__(256) gemm_kernel(const float* __restrict__ A,
                                                   const float* __restrict__ B) {
    __shared__ float As[8][128];
    __shared__ float Bs[8][128];
    int bi = blockIdx.y << 7, bj = blockIdx.x << 7;
    int t  = threadIdx.x;
    int tx = t & 15, ty = t >> 4;
    int lrow = t & 127;
    int lk   = (t >> 7) << 2;

    float acc[8][8];
#pragma unroll
    for (int i = 0; i < 8; i++)
#pragma unroll
        for (int j = 0; j < 8; j++) acc[i][j] = 0.f;

    const float* Ag = A + (size_t)(bi + lrow) * Dd + lk;
    const float* Bg = B + (size_t)(bj + lrow) * Dd + lk;

    for (int kt = 0; kt < Dd; kt += 8) {
        float4 av = *(const float4*)(Ag + kt);
        float4 bv = *(const float4*)(Bg + kt);
        __syncthreads();
        As[lk + 0][lrow] = av.x; As[lk + 1][lrow] = av.y;
        As[lk + 2][lrow] = av.z; As[lk + 3][lrow] = av.w;
        Bs[lk + 0][lrow] = bv.x; Bs[lk + 1][lrow] = bv.y;
        Bs[lk + 2][lrow] = bv.z; Bs[lk + 3][lrow] = bv.w;
        __syncthreads();
#pragma unroll
        for (int k = 0; k < 8; k++) {
            float a[8], b[8];
            *(float4*)&a[0] = *(const float4*)&As[k][(ty << 3)];
            *(float4*)&a[4] = *(const float4*)&As[k][(ty << 3) + 4];
            *(float4*)&b[0] = *(const float4*)&Bs[k][(tx << 3)];
            *(float4*)&b[4] = *(const float4*)&Bs[k][(tx << 3) + 4];
#pragma unroll
            for (int i = 0; i < 8; i++)
#pragma unroll
                for (int j = 0; j < 8; j++)
                    acc[i][j] = __fmaf_rn(a[i], b[j], acc[i][j]);
        }
    }

    int row0 = bi + (ty << 3);
    int col0 = bj + (tx << 3);
    float xs[8], ys[8];
#pragma unroll
    for (int i = 0; i < 8; i++) xs[i] = d_xsq[row0 + i];
#pragma unroll
    for (int j = 0; j < 8; j++) ys[j] = d_ysq[col0 + j];
#pragma unroll
    for (int i = 0; i < 8; i++) {
        float o[8];
#pragma unroll
        for (int j = 0; j < 8; j++) {
            float nrm  = __fadd_rn(xs[i], ys[j]);
            float cost = __fmaf_rn(-2.0f, acc[i][j], nrm);  // fused sub(2*dot) (2*dot exact)
            o[j] = __fdiv_rn(-cost, 0.1f);
        }
        *(float4*)&d_K[(size_t)(row0 + i) * Nn + col0]     = *(float4*)&o[0];
        *(float4*)&d_K[(size_t)(row0 + i) * Nn + col0 + 4] = *(float4*)&o[4];
    }
}

// =================== ROW PASS (alpha) ========================================
__global__ void __launch_bounds__(256) row_max_kernel() {
    if (g_done) return;
    int row  = blockIdx.x * 8 + (threadIdx.x >> 5);
    int lane = threadIdx.x & 31;
    const float4* Kr = (const float4*)(d_K + (size_t)row * Nn);
    const float4* Bv = (const float4*)d_beta;
    float m = __int_as_float(0xff800000);
#pragma unroll 4
    for (int k = lane; k < Nn / 4; k += 32) {
        float4 kv = Kr[k];
        float4 bv = Bv[k];
        m = fmaxf(m, fmaxf(fmaxf(__fadd_rn(kv.x, bv.x), __fadd_rn(kv.y, bv.y)),
                           fmaxf(__fadd_rn(kv.z, bv.z), __fadd_rn(kv.w, bv.w))));
    }
#pragma unroll
    for (int off = 16; off; off >>= 1)
        m = fmaxf(m, __shfl_down_sync(0xffffffffu, m, off));
    if (lane == 0) { d_m[row] = m; d_cnt[row] = 0; }
}

__global__ void __launch_bounds__(256) row_collect_kernel() {
    if (g_done) return;
    int row  = blockIdx.x * 8 + (threadIdx.x >> 5);
    int lane = threadIdx.x & 31;
    const float4* Kr = (const float4*)(d_K + (size_t)row * Nn);
    const float4* Bv = (const float4*)d_beta;
    float thr = d_m[row] - 70.0f;
#pragma unroll 4
    for (int k = lane; k < Nn / 4; k += 32) {
        float4 kv = Kr[k];
        float4 bv = Bv[k];
        float z0 = __fadd_rn(kv.x, bv.x), z1 = __fadd_rn(kv.y, bv.y);
        float z2 = __fadd_rn(kv.z, bv.z), z3 = __fadd_rn(kv.w, bv.w);
        int j = k * 4;
        if (z0 >= thr) { int p = atomicAdd(&d_cnt[row], 1); if (p < CAP) { d_cidx[(size_t)row * CAP + p] = j;     d_cz[(size_t)row * CAP + p] = z0; } }
        if (z1 >= thr) { int p = atomicAdd(&d_cnt[row], 1); if (p < CAP) { d_cidx[(size_t)row * CAP + p] = j + 1; d_cz[(size_t)row * CAP + p] = z1; } }
        if (z2 >= thr) { int p = atomicAdd(&d_cnt[row], 1); if (p < CAP) { d_cidx[(size_t)row * CAP + p] = j + 2; d_cz[(size_t)row * CAP + p] = z2; } }
        if (z3 >= thr) { int p = atomicAdd(&d_cnt[row], 1); if (p < CAP) { d_cidx[(size_t)row * CAP + p] = j + 3; d_cz[(size_t)row * CAP + p] = z3; } }
    }
}

// DIR=0 row replay: 8-slot vectorized order + halving combine (XLA reduce emitter).
// DIR=1 col replay: strictly sequential ascending i (major-dim reduce).
template <int DIR>
__global__ void __launch_bounds__(256) replay_kernel() {
    if (g_done) return;
    int r = blockIdx.x * blockDim.x + threadIdx.x;
    if (r >= Nn) return;
    float m = d_m[r];
    int cnt = d_cnt[r];
    float S;
    if (cnt <= CAP) {
        int   li[CAP];
        float lz[CAP];
        for (int p = 0; p < cnt; p++) { li[p] = d_cidx[(size_t)r * CAP + p]; lz[p] = d_cz[(size_t)r * CAP + p]; }
        for (int a = 1; a < cnt; a++) {           // sort ascending index
            int ki = li[a]; float kz = lz[a]; int b = a - 1;
            while (b >= 0 && li[b] > ki) { li[b + 1] = li[b]; lz[b + 1] = lz[b]; b--; }
            li[b + 1] = ki; lz[b + 1] = kz;
        }
        if (DIR == 0) {
            float s[8];
#pragma unroll
            for (int i = 0; i < 8; i++) s[i] = 0.0f;
            for (int p = 0; p < cnt; p++) {
                int slot = li[p] & 7;
                s[slot] = __fadd_rn(s[slot], exp_fma(__fadd_rn(lz[p], -m)));
            }
            S = combine8(s);
        } else {
            float acc = 0.0f;
            for (int p = 0; p < cnt; p++)
                acc = __fadd_rn(acc, exp_fma(__fadd_rn(lz[p], -m)));
            S = acc;
        }
    } else {
        float thr = m - 70.0f;
        if (DIR == 0) {
            float s[8];
#pragma unroll
            for (int i = 0; i < 8; i++) s[i] = 0.0f;
            for (int q = 0; q < Nn; q++) {
                float z = __fadd_rn(d_K[(size_t)r * Nn + q], d_beta[q]);
                if (z >= thr) {
                    int slot = q & 7;
                    s[slot] = __fadd_rn(s[slot], exp_fma(__fadd_rn(z, -m)));
                }
            }
            S = combine8(s);
        } else {
            float acc = 0.0f;
            for (int q = 0; q < Nn; q++) {
                float z = __fadd_rn(d_K[(size_t)q * Nn + r], d_alpha[q]);
                if (z >= thr)
                    acc = __fadd_rn(acc, exp_fma(__fadd_rn(z, -m)));
            }
            S = acc;
        }
    }
    float res = -__fadd_rn(log_fma(S), m);
    if (DIR == 0) d_alpha[r] = res; else d_beta[r] = res;
}

// =================== COLUMN PASS (beta) ======================================
__global__ void __launch_bounds__(256) col_max_part_kernel() {
    if (g_done) return;
    int j   = blockIdx.x * 256 + threadIdx.x;
    int seg = blockIdx.y;
    int i0 = seg * (Nn / 16);
    float m = __int_as_float(0xff800000);
#pragma unroll 4
    for (int i = i0; i < i0 + Nn / 16; i++) {
        float z = __fadd_rn(d_K[(size_t)i * Nn + j], d_alpha[i]);
        m = fmaxf(m, z);
    }
    d_colpart[seg * Nn + j] = m;
}

__global__ void __launch_bounds__(256) col_max_fin_kernel() {
    if (g_done) return;
    int j = blockIdx.x * 256 + threadIdx.x;
    float m = __int_as_float(0xff800000);
#pragma unroll
    for (int s = 0; s < 16; s++) m = fmaxf(m, d_colpart[s * Nn + j]);
    d_m[j] = m; d_cnt[j] = 0;
}

__global__ void __launch_bounds__(256) col_collect_kernel() {
    if (g_done) return;
    int j   = blockIdx.x * 256 + threadIdx.x;
    int seg = blockIdx.y;
    int i0 = seg * (Nn / 16);
    float thr = d_m[j] - 70.0f;
#pragma unroll 4
    for (int i = i0; i < i0 + Nn / 16; i++) {
        float z = __fadd_rn(d_K[(size_t)i * Nn + j], d_alpha[i]);
        if (z >= thr) {
            int p = atomicAdd(&d_cnt[j], 1);
            if (p < CAP) { d_cidx[(size_t)j * CAP + p] = i; d_cz[(size_t)j * CAP + p] = z; }
        }
    }
}

// ---------------- convergence: exact fp32 fixed point ----------------
__global__ void __launch_bounds__(1024) conv_kernel() {
    if (g_done) return;
    __shared__ int diff;
    if (threadIdx.x == 0) diff = 0;
    __syncthreads();
    int ld = 0;
    for (int i = threadIdx.x; i < Nn; i += 1024) {
        ld |= (__float_as_int(d_alpha[i]) != __float_as_int(d_alpha_prev[i]));
        ld |= (__float_as_int(d_beta[i])  != __float_as_int(d_beta_prev[i]));
        d_alpha_prev[i] = d_alpha[i];
        d_beta_prev[i]  = d_beta[i];
    }
    if (ld) atomicOr(&diff, 1);
    __syncthreads();
    if (threadIdx.x == 0 && diff == 0) g_done = 1;
}

// ---------------- argmax over P = exp_fma(fl(fl(K+alpha)+beta)) -------------
__global__ void __launch_bounds__(256) argmax_kernel() {
    int rowbase = blockIdx.x << 3;
    int t = threadIdx.x;
    float a[8];
#pragma unroll
    for (int r = 0; r < 8; r++) a[r] = d_alpha[rowbase + r];

    float bv[8]; int bi_[8];
#pragma unroll
    for (int r = 0; r < 8; r++) { bv[r] = -1.0f; bi_[r] = Nn; }

    for (int c = t << 2; c < Nn; c += 1024) {
        float4 betav = *(const float4*)(d_beta + c);
#pragma unroll
        for (int r = 0; r < 8; r++) {
            float4 v = *(const float4*)(d_K + (size_t)(rowbase + r) * Nn + c);
            float w;
            w = exp_fma(__fadd_rn(__fadd_rn(v.x, a[r]), betav.x)); if (w > bv[r]) { bv[r] = w; bi_[r] = c; }
            w = exp_fma(__fadd_rn(__fadd_rn(v.y, a[r]), betav.y)); if (w > bv[r]) { bv[r] = w; bi_[r] = c + 1; }
            w = exp_fma(__fadd_rn(__fadd_rn(v.z, a[r]), betav.z)); if (w > bv[r]) { bv[r] = w; bi_[r] = c + 2; }
            w = exp_fma(__fadd_rn(__fadd_rn(v.w, a[r]), betav.w)); if (w > bv[r]) { bv[r] = w; bi_[r] = c + 3; }
        }
    }
#pragma unroll
    for (int r = 0; r < 8; r++) {
#pragma unroll
        for (int off = 16; off; off >>= 1) {
            float ov = __shfl_down_sync(0xffffffffu, bv[r], off);
            int   oi = __shfl_down_sync(0xffffffffu, bi_[r], off);
            if (ov > bv[r] || (ov == bv[r] && oi < bi_[r])) { bv[r] = ov; bi_[r] = oi; }
        }
    }
    __shared__ float svv[8][8];
    __shared__ int   sii[8][8];
    int wid = t >> 5, lane = t & 31;
    if (lane == 0) {
#pragma unroll
        for (int r = 0; r < 8; r++) { svv[r][wid] = bv[r]; sii[r][wid] = bi_[r]; }
    }
    __syncthreads();
    if (t < 8) {
        float V = -1.0f; int I = Nn;
#pragma unroll
        for (int w = 0; w < 8; w++) {
            float ov = svv[t][w]; int oi = sii[t][w];
            if (ov > V || (ov == V && oi < I)) { V = ov; I = oi; }
        }
        d_idx[rowbase + t] = I;
    }
}

// ---------------- out = concat(x0, x1[idx]) ----------------
__global__ void output_kernel(const float* __restrict__ x0,
                              const float* __restrict__ x1,
                              float* __restrict__ out) {
    int row = blockIdx.x;
    int t   = threadIdx.x;
    const float4* s0 = (const float4*)(x0 + (size_t)row * Dd);
    ((float4*)(out + (size_t)row * Dd))[t] = s0[t];
    int j = d_idx[row];
    const float4* s1 = (const float4*)(x1 + (size_t)j * Dd);
    ((float4*)(out + (size_t)Nn * Dd + (size_t)row * Dd))[t] = s1[t];
}

// ---------------- launch ----------------
extern "C" void kernel_launch(void* const* d_in, const int* in_sizes, int n_in,
                              void* d_out, int out_size) {
    const float* x0 = (const float*)d_in[0];
    const float* x1 = (const float*)d_in[1];
    float* out = (float*)d_out;

    init_kernel<<<8, 1024>>>();
    rowsq_kernel<<<2 * (Nn / 256), 256>>>(x0, x1);

    dim3 gg(Nn / 128, Nn / 128);
    gemm_kernel<<<gg, 256>>>(x0, x1);

    dim3 seg2d(Nn / 256, 16);
    for (int it = 0; it < 100; it++) {
        row_max_kernel     <<<Nn / 8, 256>>>();
        row_collect_kernel <<<Nn / 8, 256>>>();
        replay_kernel<0>   <<<Nn / 256, 256>>>();
        col_max_part_kernel<<<seg2d, 256>>>();
        col_max_fin_kernel <<<Nn / 256, 256>>>();
        col_collect_kernel <<<seg2d, 256>>>();
        replay_kernel<1>   <<<Nn / 256, 256>>>();
        conv_kernel        <<<1, 1024>>>();
    }

    argmax_kernel<<<Nn / 8, 256>>>();
    output_kernel<<<Nn, 128>>>(x0, x1, out);
}